// round 13
// baseline (speedup 1.0000x reference)
#include <cuda_runtime.h>
#include <cuda_bf16.h>
#include <cstdint>

#define H_DIM 1024
#define NHEAD 16
#define DHEAD 64

// ---------------- scratch (__device__ globals; no allocs allowed) ----------
__device__ __nv_bfloat16 g_xh[3][4096 * 1024];
__device__ __nv_bfloat16 g_xl[3][4096 * 1024];
__device__ __nv_bfloat16 g_qh[4096 * 1024];
__device__ __nv_bfloat16 g_ql[4096 * 1024];
__device__ __nv_bfloat16 g_kh[4096 * 1024];
__device__ __nv_bfloat16 g_kl[4096 * 1024];
__device__ __nv_bfloat16 g_vh[4096 * 1024];
__device__ __nv_bfloat16 g_vl[4096 * 1024];
__device__ __nv_bfloat16 g_oh[4096 * 1024];
__device__ __nv_bfloat16 g_ol[4096 * 1024];
__device__ __nv_bfloat16 g_wh[4][1024 * 1024];
__device__ __nv_bfloat16 g_wl[4][1024 * 1024];

// ---------------- helpers --------------------------------------------------
__device__ __forceinline__ uint32_t smem_u32(const void* p) {
    uint32_t a;
    asm("{ .reg .u64 t; cvta.to.shared.u64 t, %1; cvt.u32.u64 %0, t; }" : "=r"(a) : "l"(p));
    return a;
}
__device__ __forceinline__ uint32_t swz(uint32_t off) {      // 128B rows
    return off ^ ((off >> 3) & 0x70);
}
__device__ __forceinline__ uint32_t swz64(uint32_t off) {    // 64B rows
    return off ^ ((off >> 3) & 0x30);
}
__device__ __forceinline__ void cp_async16(uint32_t saddr, const void* g) {
    asm volatile("cp.async.cg.shared.global [%0], [%1], 16;" :: "r"(saddr), "l"(g));
}
__device__ __forceinline__ void cp_commit() {
    asm volatile("cp.async.commit_group;" ::: "memory");
}
template <int N>
__device__ __forceinline__ void cp_wait() {
    asm volatile("cp.async.wait_group %0;" :: "n"(N) : "memory");
}
__device__ __forceinline__ void prefetch_l1(const void* g) {
    asm volatile("prefetch.global.L1 [%0];" :: "l"(g));
}
__device__ __forceinline__ void ldsm4(uint32_t* r, uint32_t addr) {
    asm volatile("ldmatrix.sync.aligned.m8n8.x4.shared.b16 {%0,%1,%2,%3}, [%4];"
                 : "=r"(r[0]), "=r"(r[1]), "=r"(r[2]), "=r"(r[3]) : "r"(addr));
}
__device__ __forceinline__ void ldsm4t(uint32_t* r, uint32_t addr) {
    asm volatile("ldmatrix.sync.aligned.m8n8.x4.trans.shared.b16 {%0,%1,%2,%3}, [%4];"
                 : "=r"(r[0]), "=r"(r[1]), "=r"(r[2]), "=r"(r[3]) : "r"(addr));
}
__device__ __forceinline__ void mma16816(float* c, const uint32_t* a, const uint32_t* b) {
    asm volatile(
        "mma.sync.aligned.m16n8k16.row.col.f32.bf16.bf16.f32 "
        "{%0,%1,%2,%3}, {%4,%5,%6,%7}, {%8,%9}, {%0,%1,%2,%3};"
        : "+f"(c[0]), "+f"(c[1]), "+f"(c[2]), "+f"(c[3])
        : "r"(a[0]), "r"(a[1]), "r"(a[2]), "r"(a[3]), "r"(b[0]), "r"(b[1]));
}
// fast splitpack: packed cvt + integer hi-reconstruction (bit-identical rn)
__device__ __forceinline__ void splitpack(float x, float y, uint32_t& hi, uint32_t& lo) {
    uint32_t h;
    asm("cvt.rn.bf16x2.f32 %0, %1, %2;" : "=r"(h) : "f"(y), "f"(x));  // hi=y, lo=x
    float xh_f = __uint_as_float(h << 16);
    float yh_f = __uint_as_float(h & 0xFFFF0000u);
    float xl = x - xh_f, yl = y - yh_f;
    uint32_t l;
    asm("cvt.rn.bf16x2.f32 %0, %1, %2;" : "=r"(l) : "f"(yl), "f"(xl));
    hi = h;
    lo = l;
}
__device__ __forceinline__ float ex2(float x) {
    float r;
    asm("ex2.approx.f32 %0, %1;" : "=f"(r) : "f"(x));
    return r;
}

// ---------------- fused conversion kernel ----------------------------------
__global__ __launch_bounds__(256) void conv_all_kernel(
    const float* __restrict__ W0, const float* __restrict__ W1,
    const float* __restrict__ W2, const float* __restrict__ W3,
    const float* __restrict__ A0, const float* __restrict__ A1,
    const float* __restrict__ A2,
    __nv_bfloat16* __restrict__ Whb, __nv_bfloat16* __restrict__ Wlb,
    __nv_bfloat16* __restrict__ Ahb, __nv_bfloat16* __restrict__ Alb, int n)
{
    const int z = blockIdx.z;
    const int tid = threadIdx.x;
    if (z < 4) {
        const float* W = (z == 0) ? W0 : (z == 1) ? W1 : (z == 2) ? W2 : W3;
        __nv_bfloat16* Wh = Whb + (size_t)z * (1024 * 1024);
        __nv_bfloat16* Wl = Wlb + (size_t)z * (1024 * 1024);
        __shared__ float t[32][33];
        int bx = blockIdx.x * 32, by = blockIdx.y * 32;
        int tx = tid & 31, ty = tid >> 5;
#pragma unroll
        for (int j = 0; j < 32; j += 8)
            t[ty + j][tx] = W[(size_t)(by + ty + j) * H_DIM + bx + tx];
        __syncthreads();
#pragma unroll
        for (int j = 0; j < 32; j += 8) {
            float v = t[tx][ty + j];
            uint32_t h;
            asm("cvt.rn.bf16x2.f32 %0, %1, %2;" : "=r"(h) : "f"(0.0f), "f"(v));
            float vh_f = __uint_as_float(h << 16);
            float vl = v - vh_f;
            size_t o = (size_t)(bx + ty + j) * H_DIM + by + tx;
            Wh[o] = __float2bfloat16(v);
            Wl[o] = __float2bfloat16(vl);
        }
    } else {
        const int zz = z - 4;
        const int tsr = zz >> 2, slice = zz & 3;
        const float* A = (tsr == 0) ? A0 : (tsr == 1) ? A1 : A2;
        __nv_bfloat16* Ah = Ahb + (size_t)tsr * n;
        __nv_bfloat16* Al = Alb + (size_t)tsr * n;
        int i = ((slice * 1024 + blockIdx.y * 32 + blockIdx.x) * 256 + tid) * 4;
        if (i >= n) return;
        float4 v = *(const float4*)(A + i);
        uint32_t h0, l0, h1, l1;
        splitpack(v.x, v.y, h0, l0);
        splitpack(v.z, v.w, h1, l1);
        *(uint32_t*)(Ah + i) = h0;
        *(uint32_t*)(Ah + i + 2) = h1;
        *(uint32_t*)(Al + i) = l0;
        *(uint32_t*)(Al + i + 2) = l1;
    }
}

// ---------------- HMMA GEMM (batched over z): C = A @ Wt^T + bias ----------
#define GK 1024
#define TILE8K 8192
#define STG32  32768
#define NSTG2  32
#define GEMM_SMEM (3 * STG32)

struct GemmArgs {
    const __nv_bfloat16 *Ah[3], *Al[3], *Bh[3], *Bl[3];
    const float* bias[3];
    float* Cf[3];
    __nv_bfloat16 *Ch[3], *Cl[3];
};

__global__ __launch_bounds__(256, 2) void hmma_gemm_kernel(GemmArgs ga)
{
    extern __shared__ char smem[];
    const uint32_t sb = smem_u32(smem);
    const int tid = threadIdx.x;
    const int wid = tid >> 5, lane = tid & 31;
    const int warp_m = wid & 1, warp_n = wid >> 1;
    const int brow = blockIdx.y * 128, bcol = blockIdx.x * 128;
    const int z = blockIdx.z;
    const int N = H_DIM;

    const __nv_bfloat16* srcs[4] = {
        ga.Ah[z] + (size_t)brow * GK, ga.Al[z] + (size_t)brow * GK,
        ga.Bh[z] + (size_t)bcol * GK, ga.Bl[z] + (size_t)bcol * GK };

    auto fill = [&](int stg) {
        const uint32_t stb = sb + (stg % 3) * STG32;
        const int k0 = stg * 32;
#pragma unroll
        for (int t = 0; t < 4; t++) {
            const __nv_bfloat16* p = srcs[t] + k0;
#pragma unroll
            for (int i = 0; i < 2; i++) {
                int idx = tid + i * 256;
                int row = idx >> 2, chk = idx & 3;
                cp_async16(stb + t * TILE8K + swz64((uint32_t)(row * 64 + chk * 16)),
                           p + (size_t)row * GK + chk * 8);
            }
        }
        cp_commit();
    };

    float c[4][4][4];
#pragma unroll
    for (int i = 0; i < 4; i++)
#pragma unroll
        for (int j = 0; j < 4; j++)
#pragma unroll
            for (int e = 0; e < 4; e++) c[i][j][e] = 0.0f;

    const int a_row = warp_m * 64 + (lane & 15);
    const int a_chk = lane >> 4;
    const int b_m  = lane >> 3, b_rl = lane & 7;
    const int b_nrow0 = warp_n * 32 + ((b_m >> 1) << 3) + b_rl;
    const uint32_t b_kb0 = (uint32_t)((b_m & 1) << 4);

    fill(0);
    fill(1);

    for (int s = 0; s < NSTG2; s++) {
        if (s + 1 < NSTG2) cp_wait<1>(); else cp_wait<0>();
        __syncthreads();          // single barrier per stage (bottom one removed:
                                  // this sync also orders prior-stage reads vs fill)
        if (s + 2 < NSTG2) fill(s + 2);

        const uint32_t stb = sb + (s % 3) * STG32;
        const uint32_t ah_b = stb, al_b = stb + TILE8K;
        const uint32_t bh_b = stb + 2 * TILE8K, bl_b = stb + 3 * TILE8K;

        uint32_t ah[2][4][4], al[2][4][4], bh[2][4][2], bl[2][4][2];

        auto load_frags = [&](int buf, int k16) {
#pragma unroll
            for (int fm = 0; fm < 4; fm++) {
                uint32_t off = swz64((uint32_t)((a_row + fm * 16) * 64 + (a_chk + 2 * k16) * 16));
                ldsm4(ah[buf][fm], ah_b + off);
                ldsm4(al[buf][fm], al_b + off);
            }
#pragma unroll
            for (int p = 0; p < 2; p++) {
                uint32_t off = swz64((uint32_t)((b_nrow0 + p * 16) * 64 + k16 * 32 + b_kb0));
                ldsm4(&bh[buf][2 * p][0], bh_b + off);
                ldsm4(&bl[buf][2 * p][0], bl_b + off);
            }
        };
        auto mma_half = [&](int buf, int fm0) {
#pragma unroll
            for (int fm = fm0; fm < fm0 + 2; fm++)
#pragma unroll
                for (int fn = 0; fn < 4; fn++) {
                    mma16816(c[fm][fn], ah[buf][fm], bh[buf][fn]);
                    mma16816(c[fm][fn], al[buf][fm], bh[buf][fn]);
                    mma16816(c[fm][fn], ah[buf][fm], bl[buf][fn]);
                }
        };

        load_frags(0, 0);
        mma_half(0, 0);
        load_frags(1, 1);
        mma_half(0, 2);
        mma_half(1, 0);
        mma_half(1, 2);
    }

    const int erow = brow + warp_m * 64 + (lane >> 2);
    const int ecol = bcol + warp_n * 32 + 2 * (lane & 3);
    float* Cf = ga.Cf[z];
    __nv_bfloat16* Ch = ga.Ch[z];
    __nv_bfloat16* Cl = ga.Cl[z];
#pragma unroll
    for (int fn = 0; fn < 4; fn++) {
        const int col = ecol + fn * 8;
        const float2 bv = *(const float2*)(ga.bias[z] + col);
#pragma unroll
        for (int fm = 0; fm < 4; fm++) {
            const int r0 = erow + fm * 16;
            float v00 = c[fm][fn][0] + bv.x, v01 = c[fm][fn][1] + bv.y;
            float v10 = c[fm][fn][2] + bv.x, v11 = c[fm][fn][3] + bv.y;
            if (Cf) {
                *(float2*)(Cf + (size_t)r0 * N + col) = make_float2(v00, v01);
                *(float2*)(Cf + (size_t)(r0 + 8) * N + col) = make_float2(v10, v11);
            } else {
                uint32_t h0, l0, h1, l1;
                splitpack(v00, v01, h0, l0);
                splitpack(v10, v11, h1, l1);
                *(uint32_t*)(Ch + (size_t)r0 * N + col) = h0;
                *(uint32_t*)(Cl + (size_t)r0 * N + col) = l0;
                *(uint32_t*)(Ch + (size_t)(r0 + 8) * N + col) = h1;
                *(uint32_t*)(Cl + (size_t)(r0 + 8) * N + col) = l1;
            }
        }
    }
}

// ---------------- HMMA flash attention (interleaved deferred-PV) -----------
#define ATT_STG  32768
#define ATT_SMEM (3 * ATT_STG)

__global__ __launch_bounds__(128, 2) void hmma_attn_kernel(
    const __nv_bfloat16* __restrict__ Qh, const __nv_bfloat16* __restrict__ Ql,
    const __nv_bfloat16* __restrict__ Kh, const __nv_bfloat16* __restrict__ Kl,
    const __nv_bfloat16* __restrict__ Vh, const __nv_bfloat16* __restrict__ Vl,
    const int* __restrict__ mask,
    __nv_bfloat16* __restrict__ Oh, __nv_bfloat16* __restrict__ Ol, int S)
{
    extern __shared__ char smem[];
    const uint32_t sb = smem_u32(smem);
    const int tid = threadIdx.x, wid = tid >> 5, lane = tid & 31;
    const int qt = blockIdx.x, h = blockIdx.y, b = blockIdx.z;

    const size_t bh = (size_t)b * S * H_DIM + h * DHEAD;
    const __nv_bfloat16* srcs[4] = { Kh + bh, Kl + bh, Vh + bh, Vl + bh };

    // ---- Q tile -> smem (transient, overlaps stage 0) -> registers ----
    {
        const size_t qoff = bh + (size_t)qt * 64 * H_DIM;
#pragma unroll
        for (int i = 0; i < 8; i++) {
            int idx = tid + i * 128;
            int t = idx >> 9, row = (idx >> 3) & 63, chk = idx & 7;
            const __nv_bfloat16* g = (t ? Ql : Qh) + qoff + (size_t)row * H_DIM + chk * 8;
            cp_async16(sb + t * 8192 + swz(row * 128 + chk * 16), g);
        }
    }
    cp_commit();
    cp_wait<0>();
    __syncthreads();

    uint32_t qfh[4][4], qfl[4][4];
    {
        const int row = wid * 16 + (lane & 15);
#pragma unroll
        for (int j = 0; j < 4; j++) {
            uint32_t off = swz((uint32_t)(row * 128 + (2 * j + (lane >> 4)) * 16));
            ldsm4(qfh[j], sb + off);
            ldsm4(qfl[j], sb + 8192 + off);
        }
    }
#pragma unroll
    for (int j = 0; j < 4; j++)
        asm volatile("" :: "r"(qfh[j][0]), "r"(qfl[j][0]));
    __syncthreads();

    auto fillkv = [&](int stg, int kt) {
        const uint32_t stb = sb + stg * ATT_STG;
#pragma unroll
        for (int i = 0; i < 16; i++) {
            int idx = tid + i * 128;
            int t = idx >> 9, row = (idx >> 3) & 63, chk = idx & 7;
            const __nv_bfloat16* g = srcs[t] + (size_t)(kt * 64 + row) * H_DIM + chk * 8;
            cp_async16(stb + t * 8192 + swz(row * 128 + chk * 16), g);
        }
        cp_commit();
    };
    fillkv(0, 0);
    fillkv(1, 1);

    float o[8][4];
#pragma unroll
    for (int i = 0; i < 8; i++)
#pragma unroll
        for (int e = 0; e < 4; e++) o[i][e] = 0.0f;
    float m0 = -1e30f, m1 = -1e30f, l0 = 0.0f, l1 = 0.0f;

    uint32_t pah_s[4][4], pal_s[4][4];
#pragma unroll
    for (int j = 0; j < 4; j++)
#pragma unroll
        for (int e = 0; e < 4; e++) { pah_s[j][e] = 0u; pal_s[j][e] = 0u; }

    const int grow = qt * 64 + wid * 16 + (lane >> 2);
    const int* mbase = mask + (size_t)b * S * S + (size_t)grow * S + 2 * (lane & 3);

    const int k_m = lane >> 3, k_rl = lane & 7;
    const int k_row0 = ((k_m >> 1) << 3) + k_rl;
    const uint32_t k_kb0 = (uint32_t)((k_m & 1) << 4);

    const float SC2 = 0.18033688011f;   // 0.125 * log2(e)
    const int nch = S / 64;

    for (int c = 0; c < nch; c++) {
        if (c + 1 < nch) cp_wait<1>(); else cp_wait<0>();
        __syncthreads();
        const uint32_t stK = sb + (c % 3) * ATT_STG;
        const uint32_t stV = sb + (c > 0 ? (c - 1) % 3 : 0) * ATT_STG;

        // ---- prefetch this chunk's mask rows to L1 (covered by QK MMAs) ----
        const int* mr = mbase + c * 64;
#pragma unroll
        for (int nt = 0; nt < 8; nt++) {
            prefetch_l1(mr + nt * 8);
            prefetch_l1(mr + 8 * S + nt * 8);
        }

        // ---- QK^T (3-term split) -> s ----
        float s[8][4];
#pragma unroll
        for (int nt = 0; nt < 8; nt++)
#pragma unroll
            for (int e = 0; e < 4; e++) s[nt][e] = 0.0f;

#pragma unroll
        for (int j = 0; j < 4; j++) {
#pragma unroll
            for (int p = 0; p < 4; p++) {
                uint32_t off = swz((uint32_t)((p * 16 + k_row0) * 128 + j * 32 + k_kb0));
                uint32_t kb[4], kbl[4];
                ldsm4(kb, stK + off);
                ldsm4(kbl, stK + 8192 + off);
                mma16816(s[2 * p], qfh[j], kb);
                mma16816(s[2 * p], qfl[j], kb);
                mma16816(s[2 * p], qfh[j], kbl);
                mma16816(s[2 * p + 1], qfh[j], kb + 2);
                mma16816(s[2 * p + 1], qfl[j], kb + 2);
                mma16816(s[2 * p + 1], qfh[j], kbl + 2);
            }
        }

        auto pv_block = [&](int j) {
#pragma unroll
            for (int db = 0; db < 4; db++) {
                uint32_t off = swz((uint32_t)((j * 16 + (lane & 15)) * 128
                                              + (db * 2 + (lane >> 4)) * 16));
                uint32_t vfh[4], vfl[4];
                ldsm4t(vfh, stV + 16384 + off);
                ldsm4t(vfl, stV + 24576 + off);
                mma16816(o[db * 2], pah_s[j], vfh);
                mma16816(o[db * 2], pal_s[j], vfh);
                mma16816(o[db * 2], pah_s[j], vfl);
                mma16816(o[db * 2 + 1], pah_s[j], vfh + 2);
                mma16816(o[db * 2 + 1], pal_s[j], vfh + 2);
                mma16816(o[db * 2 + 1], pah_s[j], vfl + 2);
            }
        };

        // ---- phase 1: mask (L1-hot) + scale into log2 domain ----
#pragma unroll
        for (int nt = 0; nt < 8; nt++) {
            int2 ma = *(const int2*)(mr + nt * 8);
            int2 mb2 = *(const int2*)(mr + 8 * S + nt * 8);
            s[nt][0] = (ma.x == 0) ? -14427.0f : s[nt][0] * SC2;
            s[nt][1] = (ma.y == 0) ? -14427.0f : s[nt][1] * SC2;
            s[nt][2] = (mb2.x == 0) ? -14427.0f : s[nt][2] * SC2;
            s[nt][3] = (mb2.y == 0) ? -14427.0f : s[nt][3] * SC2;
        }

        pv_block(0);

        // ---- phase 2: local max reduce ----
        float mx0 = -1e30f, mx1 = -1e30f;
#pragma unroll
        for (int nt = 0; nt < 8; nt++) {
            mx0 = fmaxf(mx0, fmaxf(s[nt][0], s[nt][1]));
            mx1 = fmaxf(mx1, fmaxf(s[nt][2], s[nt][3]));
        }

        pv_block(1);

        // ---- phase 3: max shuffles + new maxima ----
        mx0 = fmaxf(mx0, __shfl_xor_sync(0xffffffffu, mx0, 1));
        mx0 = fmaxf(mx0, __shfl_xor_sync(0xffffffffu, mx0, 2));
        mx1 = fmaxf(mx1, __shfl_xor_sync(0xffffffffu, mx1, 1));
        mx1 = fmaxf(mx1, __shfl_xor_sync(0xffffffffu, mx1, 2));
        float mn0 = fmaxf(m0, mx0), mn1 = fmaxf(m1, mx1);
        float d0 = m0 - mn0, d1 = m1 - mn1;
        bool unchanged = (d0 == 0.0f) && (d1 == 0.0f);
        m0 = mn0;
        m1 = mn1;

        pv_block(2);

        // ---- phase 4: ALL exponentials + local sums ----
        float rs0 = 0.0f, rs1 = 0.0f;
#pragma unroll
        for (int nt = 0; nt < 8; nt++) {
            s[nt][0] = ex2(s[nt][0] - mn0);
            s[nt][1] = ex2(s[nt][1] - mn0);
            s[nt][2] = ex2(s[nt][2] - mn1);
            s[nt][3] = ex2(s[nt][3] - mn1);
            rs0 += s[nt][0] + s[nt][1];
            rs1 += s[nt][2] + s[nt][3];
        }

        // ---- splitpack first half (pv(0),(1) already consumed pah_s[0,1]) ----
#pragma unroll
        for (int j = 0; j < 2; j++) {
            splitpack(s[2 * j][0], s[2 * j][1], pah_s[j][0], pal_s[j][0]);
            splitpack(s[2 * j][2], s[2 * j][3], pah_s[j][1], pal_s[j][1]);
            splitpack(s[2 * j + 1][0], s[2 * j + 1][1], pah_s[j][2], pal_s[j][2]);
            splitpack(s[2 * j + 1][2], s[2 * j + 1][3], pah_s[j][3], pal_s[j][3]);
        }

        pv_block(3);

        // ---- phase 5: sum shuffles + l update + join rescale ----
        rs0 += __shfl_xor_sync(0xffffffffu, rs0, 1);
        rs0 += __shfl_xor_sync(0xffffffffu, rs0, 2);
        rs1 += __shfl_xor_sync(0xffffffffu, rs1, 1);
        rs1 += __shfl_xor_sync(0xffffffffu, rs1, 2);
        if (__all_sync(0xffffffffu, unchanged)) {
            l0 += rs0;
            l1 += rs1;
        } else {
            float cr0 = ex2(d0), cr1 = ex2(d1);
            l0 = l0 * cr0 + rs0;
            l1 = l1 * cr1 + rs1;
#pragma unroll
            for (int nt = 0; nt < 8; nt++) {
                o[nt][0] *= cr0;
                o[nt][1] *= cr0;
                o[nt][2] *= cr1;
                o[nt][3] *= cr1;
            }
        }

        // ---- splitpack second half ----
#pragma unroll
        for (int j = 2; j < 4; j++) {
            splitpack(s[2 * j][0], s[2 * j][1], pah_s[j][0], pal_s[j][0]);
            splitpack(s[2 * j][2], s[2 * j][3], pah_s[j][1], pal_s[j][1]);
            splitpack(s[2 * j + 1][0], s[2 * j + 1][1], pah_s[j][2], pal_s[j][2]);
            splitpack(s[2 * j + 1][2], s[2 * j + 1][3], pah_s[j][3], pal_s[j][3]);
        }

        __syncthreads();                 // V(c-1) reads complete before overwrite
        if (c + 2 < nch) fillkv((c + 2) % 3, c + 2);
    }

    // ---- final pending PV(nch-1) ----
    {
        const uint32_t stV = sb + ((nch - 1) % 3) * ATT_STG;
#pragma unroll
        for (int j = 0; j < 4; j++) {
#pragma unroll
            for (int db = 0; db < 4; db++) {
                uint32_t off = swz((uint32_t)((j * 16 + (lane & 15)) * 128
                                              + (db * 2 + (lane >> 4)) * 16));
                uint32_t vfh[4], vfl[4];
                ldsm4t(vfh, stV + 16384 + off);
                ldsm4t(vfl, stV + 24576 + off);
                mma16816(o[db * 2], pah_s[j], vfh);
                mma16816(o[db * 2], pal_s[j], vfh);
                mma16816(o[db * 2], pah_s[j], vfl);
                mma16816(o[db * 2 + 1], pah_s[j], vfh + 2);
                mma16816(o[db * 2 + 1], pal_s[j], vfh + 2);
                mma16816(o[db * 2 + 1], pah_s[j], vfl + 2);
            }
        }
    }

    const float i0 = 1.0f / l0, i1 = 1.0f / l1;
    const size_t ob = (size_t)(b * S + grow) * H_DIM + h * DHEAD + 2 * (lane & 3);
#pragma unroll
    for (int nt = 0; nt < 8; nt++) {
        uint32_t h0, lo0, h1, lo1;
        splitpack(o[nt][0] * i0, o[nt][1] * i0, h0, lo0);
        splitpack(o[nt][2] * i1, o[nt][3] * i1, h1, lo1);
        *(uint32_t*)(Oh + ob + nt * 8) = h0;
        *(uint32_t*)(Ol + ob + nt * 8) = lo0;
        *(uint32_t*)(Oh + ob + 8 * H_DIM + nt * 8) = h1;
        *(uint32_t*)(Ol + ob + 8 * H_DIM + nt * 8) = lo1;
    }
}

// ---------------- launch ---------------------------------------------------
extern "C" void kernel_launch(void* const* d_in, const int* in_sizes, int n_in,
                              void* d_out, int out_size)
{
    const float* q   = (const float*)d_in[0];
    const float* k   = (const float*)d_in[1];
    const float* v   = (const float*)d_in[2];
    const int*   msk = (const int*)d_in[3];
    const float* w_q = (const float*)d_in[4];
    const float* b_q = (const float*)d_in[5];
    const float* w_k = (const float*)d_in[6];
    const float* b_k = (const float*)d_in[7];
    const float* w_v = (const float*)d_in[8];
    const float* b_v = (const float*)d_in[9];
    const float* w_o = (const float*)d_in[10];
    const float* b_o = (const float*)d_in[11];
    float* out = (float*)d_out;

    const int BS = in_sizes[0] / H_DIM;
    const int S  = in_sizes[3] / BS;
    const int B  = BS / S;
    const int M  = BS;
    const int n_elem = M * H_DIM;

    __nv_bfloat16 *xh, *xl, *qh, *ql, *kh, *kl, *vh, *vl, *oh, *ol, *wh, *wl;
    cudaGetSymbolAddress((void**)&xh, g_xh);
    cudaGetSymbolAddress((void**)&xl, g_xl);
    cudaGetSymbolAddress((void**)&qh, g_qh);
    cudaGetSymbolAddress((void**)&ql, g_ql);
    cudaGetSymbolAddress((void**)&kh, g_kh);
    cudaGetSymbolAddress((void**)&kl, g_kl);
    cudaGetSymbolAddress((void**)&vh, g_vh);
    cudaGetSymbolAddress((void**)&vl, g_vl);
    cudaGetSymbolAddress((void**)&oh, g_oh);
    cudaGetSymbolAddress((void**)&ol, g_ol);
    cudaGetSymbolAddress((void**)&wh, g_wh);
    cudaGetSymbolAddress((void**)&wl, g_wl);

    cudaFuncSetAttribute(hmma_gemm_kernel,
                         cudaFuncAttributeMaxDynamicSharedMemorySize, GEMM_SMEM);
    cudaFuncSetAttribute(hmma_attn_kernel,
                         cudaFuncAttributeMaxDynamicSharedMemorySize, ATT_SMEM);

    const size_t WSZ = 1024 * 1024;

    // all conversions in ONE launch
    conv_all_kernel<<<dim3(32, 32, 16), 256>>>(
        w_q, w_k, w_v, w_o, q, k, v, wh, wl, xh, xl, n_elem);

    // QKV projections in ONE launch (z = 0,1,2)
    {
        GemmArgs ga;
        for (int z = 0; z < 3; z++) {
            ga.Ah[z] = xh + (size_t)z * n_elem;
            ga.Al[z] = xl + (size_t)z * n_elem;
            ga.Bh[z] = wh + (size_t)z * WSZ;
            ga.Bl[z] = wl + (size_t)z * WSZ;
            ga.Cf[z] = nullptr;
        }
        ga.bias[0] = b_q; ga.bias[1] = b_k; ga.bias[2] = b_v;
        ga.Ch[0] = qh; ga.Cl[0] = ql;
        ga.Ch[1] = kh; ga.Cl[1] = kl;
        ga.Ch[2] = vh; ga.Cl[2] = vl;
        hmma_gemm_kernel<<<dim3(H_DIM / 128, M / 128, 3), 256, GEMM_SMEM>>>(ga);
    }

    // attention
    hmma_attn_kernel<<<dim3(S / 64, NHEAD, B), 128, ATT_SMEM>>>(
        qh, ql, kh, kl, vh, vl, msk, oh, ol, S);

    // O projection -> fp32 out
    {
        GemmArgs ga;
        ga.Ah[0] = oh; ga.Al[0] = ol;
        ga.Bh[0] = wh + 3 * WSZ; ga.Bl[0] = wl + 3 * WSZ;
        ga.bias[0] = b_o;
        ga.Cf[0] = out; ga.Ch[0] = nullptr; ga.Cl[0] = nullptr;
        ga.Ah[1] = ga.Ah[2] = oh; ga.Al[1] = ga.Al[2] = ol;
        ga.Bh[1] = ga.Bh[2] = wh; ga.Bl[1] = ga.Bl[2] = wl;
        ga.bias[1] = ga.bias[2] = b_o;
        ga.Cf[1] = ga.Cf[2] = nullptr;
        ga.Ch[1] = ga.Ch[2] = nullptr; ga.Cl[1] = ga.Cl[2] = nullptr;
        hmma_gemm_kernel<<<dim3(H_DIM / 128, M / 128, 1), 256, GEMM_SMEM>>>(ga);
    }
}

// round 14
// speedup vs baseline: 1.6074x; 1.6074x over previous
#include <cuda_runtime.h>
#include <cuda_bf16.h>
#include <cstdint>

#define H_DIM 1024
#define NHEAD 16
#define DHEAD 64

// ---------------- scratch (__device__ globals; no allocs allowed) ----------
__device__ __nv_bfloat16 g_xh[3][4096 * 1024];
__device__ __nv_bfloat16 g_xl[3][4096 * 1024];
__device__ __nv_bfloat16 g_qh[4096 * 1024];
__device__ __nv_bfloat16 g_ql[4096 * 1024];
__device__ __nv_bfloat16 g_kh[4096 * 1024];
__device__ __nv_bfloat16 g_kl[4096 * 1024];
__device__ __nv_bfloat16 g_vh[4096 * 1024];
__device__ __nv_bfloat16 g_vl[4096 * 1024];
__device__ __nv_bfloat16 g_oh[4096 * 1024];
__device__ __nv_bfloat16 g_ol[4096 * 1024];
__device__ __nv_bfloat16 g_wh[4][1024 * 1024];
__device__ __nv_bfloat16 g_wl[4][1024 * 1024];

// ---------------- helpers --------------------------------------------------
__device__ __forceinline__ uint32_t smem_u32(const void* p) {
    uint32_t a;
    asm("{ .reg .u64 t; cvta.to.shared.u64 t, %1; cvt.u32.u64 %0, t; }" : "=r"(a) : "l"(p));
    return a;
}
__device__ __forceinline__ uint32_t swz(uint32_t off) {      // 128B rows
    return off ^ ((off >> 3) & 0x70);
}
__device__ __forceinline__ uint32_t swz64(uint32_t off) {    // 64B rows
    return off ^ ((off >> 3) & 0x30);
}
__device__ __forceinline__ void cp_async16(uint32_t saddr, const void* g) {
    asm volatile("cp.async.cg.shared.global [%0], [%1], 16;" :: "r"(saddr), "l"(g));
}
__device__ __forceinline__ void cp_commit() {
    asm volatile("cp.async.commit_group;" ::: "memory");
}
template <int N>
__device__ __forceinline__ void cp_wait() {
    asm volatile("cp.async.wait_group %0;" :: "n"(N) : "memory");
}
__device__ __forceinline__ void ldsm4(uint32_t* r, uint32_t addr) {
    asm volatile("ldmatrix.sync.aligned.m8n8.x4.shared.b16 {%0,%1,%2,%3}, [%4];"
                 : "=r"(r[0]), "=r"(r[1]), "=r"(r[2]), "=r"(r[3]) : "r"(addr));
}
__device__ __forceinline__ void ldsm4t(uint32_t* r, uint32_t addr) {
    asm volatile("ldmatrix.sync.aligned.m8n8.x4.trans.shared.b16 {%0,%1,%2,%3}, [%4];"
                 : "=r"(r[0]), "=r"(r[1]), "=r"(r[2]), "=r"(r[3]) : "r"(addr));
}
__device__ __forceinline__ void mma16816(float* c, const uint32_t* a, const uint32_t* b) {
    asm volatile(
        "mma.sync.aligned.m16n8k16.row.col.f32.bf16.bf16.f32 "
        "{%0,%1,%2,%3}, {%4,%5,%6,%7}, {%8,%9}, {%0,%1,%2,%3};"
        : "+f"(c[0]), "+f"(c[1]), "+f"(c[2]), "+f"(c[3])
        : "r"(a[0]), "r"(a[1]), "r"(a[2]), "r"(a[3]), "r"(b[0]), "r"(b[1]));
}
// fast splitpack: packed cvt + integer hi-reconstruction (bit-identical rn)
__device__ __forceinline__ void splitpack(float x, float y, uint32_t& hi, uint32_t& lo) {
    uint32_t h;
    asm("cvt.rn.bf16x2.f32 %0, %1, %2;" : "=r"(h) : "f"(y), "f"(x));  // hi=y, lo=x
    float xh_f = __uint_as_float(h << 16);
    float yh_f = __uint_as_float(h & 0xFFFF0000u);
    float xl = x - xh_f, yl = y - yh_f;
    uint32_t l;
    asm("cvt.rn.bf16x2.f32 %0, %1, %2;" : "=r"(l) : "f"(yl), "f"(xl));
    hi = h;
    lo = l;
}
__device__ __forceinline__ float ex2(float x) {
    float r;
    asm("ex2.approx.f32 %0, %1;" : "=f"(r) : "f"(x));
    return r;
}

// ---------------- fused conversion kernel ----------------------------------
// z 0..3  : transpose+split weight z  ([K,N] -> [N,K] hi/lo)
// z 4..15 : split activation (z-4)/4, slice (z-4)%4
__global__ __launch_bounds__(256) void conv_all_kernel(
    const float* __restrict__ W0, const float* __restrict__ W1,
    const float* __restrict__ W2, const float* __restrict__ W3,
    const float* __restrict__ A0, const float* __restrict__ A1,
    const float* __restrict__ A2,
    __nv_bfloat16* __restrict__ Whb, __nv_bfloat16* __restrict__ Wlb,
    __nv_bfloat16* __restrict__ Ahb, __nv_bfloat16* __restrict__ Alb, int n)
{
    const int z = blockIdx.z;
    const int tid = threadIdx.x;
    if (z < 4) {
        const float* W = (z == 0) ? W0 : (z == 1) ? W1 : (z == 2) ? W2 : W3;
        __nv_bfloat16* Wh = Whb + (size_t)z * (1024 * 1024);
        __nv_bfloat16* Wl = Wlb + (size_t)z * (1024 * 1024);
        __shared__ float t[32][33];
        int bx = blockIdx.x * 32, by = blockIdx.y * 32;
        int tx = tid & 31, ty = tid >> 5;
#pragma unroll
        for (int j = 0; j < 32; j += 8)
            t[ty + j][tx] = W[(size_t)(by + ty + j) * H_DIM + bx + tx];
        __syncthreads();
#pragma unroll
        for (int j = 0; j < 32; j += 8) {
            float v = t[tx][ty + j];
            uint32_t h;
            asm("cvt.rn.bf16x2.f32 %0, %1, %2;" : "=r"(h) : "f"(0.0f), "f"(v));
            float vh_f = __uint_as_float(h << 16);
            float vl = v - vh_f;
            size_t o = (size_t)(bx + ty + j) * H_DIM + by + tx;
            Wh[o] = __float2bfloat16(v);
            Wl[o] = __float2bfloat16(vl);
        }
    } else {
        const int zz = z - 4;
        const int tsr = zz >> 2, slice = zz & 3;
        const float* A = (tsr == 0) ? A0 : (tsr == 1) ? A1 : A2;
        __nv_bfloat16* Ah = Ahb + (size_t)tsr * n;
        __nv_bfloat16* Al = Alb + (size_t)tsr * n;
        int i = ((slice * 1024 + blockIdx.y * 32 + blockIdx.x) * 256 + tid) * 4;
        if (i >= n) return;
        float4 v = *(const float4*)(A + i);
        uint32_t h0, l0, h1, l1;
        splitpack(v.x, v.y, h0, l0);
        splitpack(v.z, v.w, h1, l1);
        *(uint32_t*)(Ah + i) = h0;
        *(uint32_t*)(Ah + i + 2) = h1;
        *(uint32_t*)(Al + i) = l0;
        *(uint32_t*)(Al + i + 2) = l1;
    }
}

// ---------------- HMMA GEMM (batched over z): C = A @ Wt^T + bias ----------
#define GK 1024
#define TILE8K 8192
#define STG32  32768
#define NSTG2  32
#define GEMM_SMEM (3 * STG32)

struct GemmArgs {
    const __nv_bfloat16 *Ah[3], *Al[3], *Bh[3], *Bl[3];
    const float* bias[3];
    float* Cf[3];
    __nv_bfloat16 *Ch[3], *Cl[3];
};

__global__ __launch_bounds__(256, 2) void hmma_gemm_kernel(GemmArgs ga)
{
    extern __shared__ char smem[];
    const uint32_t sb = smem_u32(smem);
    const int tid = threadIdx.x;
    const int wid = tid >> 5, lane = tid & 31;
    const int warp_m = wid & 1, warp_n = wid >> 1;
    const int brow = blockIdx.y * 128, bcol = blockIdx.x * 128;
    const int z = blockIdx.z;
    const int N = H_DIM;

    const __nv_bfloat16* srcs[4] = {
        ga.Ah[z] + (size_t)brow * GK, ga.Al[z] + (size_t)brow * GK,
        ga.Bh[z] + (size_t)bcol * GK, ga.Bl[z] + (size_t)bcol * GK };

    auto fill = [&](int stg) {
        const uint32_t stb = sb + (stg % 3) * STG32;
        const int k0 = stg * 32;
#pragma unroll
        for (int t = 0; t < 4; t++) {
            const __nv_bfloat16* p = srcs[t] + k0;
#pragma unroll
            for (int i = 0; i < 2; i++) {
                int idx = tid + i * 256;
                int row = idx >> 2, chk = idx & 3;
                cp_async16(stb + t * TILE8K + swz64((uint32_t)(row * 64 + chk * 16)),
                           p + (size_t)row * GK + chk * 8);
            }
        }
        cp_commit();
    };

    float c[4][4][4];
#pragma unroll
    for (int i = 0; i < 4; i++)
#pragma unroll
        for (int j = 0; j < 4; j++)
#pragma unroll
            for (int e = 0; e < 4; e++) c[i][j][e] = 0.0f;

    const int a_row = warp_m * 64 + (lane & 15);
    const int a_chk = lane >> 4;
    const int b_m  = lane >> 3, b_rl = lane & 7;
    const int b_nrow0 = warp_n * 32 + ((b_m >> 1) << 3) + b_rl;
    const uint32_t b_kb0 = (uint32_t)((b_m & 1) << 4);

    fill(0);
    fill(1);

    for (int s = 0; s < NSTG2; s++) {
        if (s + 1 < NSTG2) cp_wait<1>(); else cp_wait<0>();
        __syncthreads();
        if (s + 2 < NSTG2) fill(s + 2);

        const uint32_t stb = sb + (s % 3) * STG32;
        const uint32_t ah_b = stb, al_b = stb + TILE8K;
        const uint32_t bh_b = stb + 2 * TILE8K, bl_b = stb + 3 * TILE8K;

        // double-buffered fragments over the two k16 steps
        uint32_t ah[2][4][4], al[2][4][4], bh[2][4][2], bl[2][4][2];

        auto load_frags = [&](int buf, int k16) {
#pragma unroll
            for (int fm = 0; fm < 4; fm++) {
                uint32_t off = swz64((uint32_t)((a_row + fm * 16) * 64 + (a_chk + 2 * k16) * 16));
                ldsm4(ah[buf][fm], ah_b + off);
                ldsm4(al[buf][fm], al_b + off);
            }
#pragma unroll
            for (int p = 0; p < 2; p++) {
                uint32_t off = swz64((uint32_t)((b_nrow0 + p * 16) * 64 + k16 * 32 + b_kb0));
                ldsm4(&bh[buf][2 * p][0], bh_b + off);
                ldsm4(&bl[buf][2 * p][0], bl_b + off);
            }
        };
        auto mma_half = [&](int buf, int fm0) {
#pragma unroll
            for (int fm = fm0; fm < fm0 + 2; fm++)
#pragma unroll
                for (int fn = 0; fn < 4; fn++) {
                    mma16816(c[fm][fn], ah[buf][fm], bh[buf][fn]);
                    mma16816(c[fm][fn], al[buf][fm], bh[buf][fn]);
                    mma16816(c[fm][fn], ah[buf][fm], bl[buf][fn]);
                }
        };

        load_frags(0, 0);
        mma_half(0, 0);
        load_frags(1, 1);      // overlaps with remaining k16=0 MMAs
        mma_half(0, 2);
        mma_half(1, 0);
        mma_half(1, 2);

        __syncthreads();
    }

    const int erow = brow + warp_m * 64 + (lane >> 2);
    const int ecol = bcol + warp_n * 32 + 2 * (lane & 3);
    float* Cf = ga.Cf[z];
    __nv_bfloat16* Ch = ga.Ch[z];
    __nv_bfloat16* Cl = ga.Cl[z];
#pragma unroll
    for (int fn = 0; fn < 4; fn++) {
        const int col = ecol + fn * 8;
        const float2 bv = *(const float2*)(ga.bias[z] + col);
#pragma unroll
        for (int fm = 0; fm < 4; fm++) {
            const int r0 = erow + fm * 16;
            float v00 = c[fm][fn][0] + bv.x, v01 = c[fm][fn][1] + bv.y;
            float v10 = c[fm][fn][2] + bv.x, v11 = c[fm][fn][3] + bv.y;
            if (Cf) {
                *(float2*)(Cf + (size_t)r0 * N + col) = make_float2(v00, v01);
                *(float2*)(Cf + (size_t)(r0 + 8) * N + col) = make_float2(v10, v11);
            } else {
                uint32_t h0, l0, h1, l1;
                splitpack(v00, v01, h0, l0);
                splitpack(v10, v11, h1, l1);
                *(uint32_t*)(Ch + (size_t)r0 * N + col) = h0;
                *(uint32_t*)(Cl + (size_t)r0 * N + col) = l0;
                *(uint32_t*)(Ch + (size_t)(r0 + 8) * N + col) = h1;
                *(uint32_t*)(Cl + (size_t)(r0 + 8) * N + col) = l1;
            }
        }
    }
}

// ---------------- HMMA flash attention (interleaved deferred-PV) -----------
#define ATT_STG  32768
#define ATT_SMEM (3 * ATT_STG)

__global__ __launch_bounds__(128, 2) void hmma_attn_kernel(
    const __nv_bfloat16* __restrict__ Qh, const __nv_bfloat16* __restrict__ Ql,
    const __nv_bfloat16* __restrict__ Kh, const __nv_bfloat16* __restrict__ Kl,
    const __nv_bfloat16* __restrict__ Vh, const __nv_bfloat16* __restrict__ Vl,
    const int* __restrict__ mask,
    __nv_bfloat16* __restrict__ Oh, __nv_bfloat16* __restrict__ Ol, int S)
{
    extern __shared__ char smem[];
    const uint32_t sb = smem_u32(smem);
    const int tid = threadIdx.x, wid = tid >> 5, lane = tid & 31;
    const int qt = blockIdx.x, h = blockIdx.y, b = blockIdx.z;

    const size_t bh = (size_t)b * S * H_DIM + h * DHEAD;
    const __nv_bfloat16* srcs[4] = { Kh + bh, Kl + bh, Vh + bh, Vl + bh };

    // ---- Q tile -> smem (transient, overlaps stage 0) -> registers ----
    {
        const size_t qoff = bh + (size_t)qt * 64 * H_DIM;
#pragma unroll
        for (int i = 0; i < 8; i++) {
            int idx = tid + i * 128;
            int t = idx >> 9, row = (idx >> 3) & 63, chk = idx & 7;
            const __nv_bfloat16* g = (t ? Ql : Qh) + qoff + (size_t)row * H_DIM + chk * 8;
            cp_async16(sb + t * 8192 + swz(row * 128 + chk * 16), g);
        }
    }
    cp_commit();
    cp_wait<0>();
    __syncthreads();

    uint32_t qfh[4][4], qfl[4][4];
    {
        const int row = wid * 16 + (lane & 15);
#pragma unroll
        for (int j = 0; j < 4; j++) {
            uint32_t off = swz((uint32_t)(row * 128 + (2 * j + (lane >> 4)) * 16));
            ldsm4(qfh[j], sb + off);
            ldsm4(qfl[j], sb + 8192 + off);
        }
    }
#pragma unroll
    for (int j = 0; j < 4; j++)
        asm volatile("" :: "r"(qfh[j][0]), "r"(qfl[j][0]));
    __syncthreads();

    auto fillkv = [&](int stg, int kt) {
        const uint32_t stb = sb + stg * ATT_STG;
#pragma unroll
        for (int i = 0; i < 16; i++) {
            int idx = tid + i * 128;
            int t = idx >> 9, row = (idx >> 3) & 63, chk = idx & 7;
            const __nv_bfloat16* g = srcs[t] + (size_t)(kt * 64 + row) * H_DIM + chk * 8;
            cp_async16(stb + t * 8192 + swz(row * 128 + chk * 16), g);
        }
        cp_commit();
    };
    fillkv(0, 0);
    fillkv(1, 1);

    float o[8][4];
#pragma unroll
    for (int i = 0; i < 8; i++)
#pragma unroll
        for (int e = 0; e < 4; e++) o[i][e] = 0.0f;
    float m0 = -1e30f, m1 = -1e30f, l0 = 0.0f, l1 = 0.0f;

    uint32_t pah_s[4][4], pal_s[4][4];
#pragma unroll
    for (int j = 0; j < 4; j++)
#pragma unroll
        for (int e = 0; e < 4; e++) { pah_s[j][e] = 0u; pal_s[j][e] = 0u; }

    const int grow = qt * 64 + wid * 16 + (lane >> 2);
    const int* mbase = mask + (size_t)b * S * S + (size_t)grow * S + 2 * (lane & 3);

    const int k_m = lane >> 3, k_rl = lane & 7;
    const int k_row0 = ((k_m >> 1) << 3) + k_rl;
    const uint32_t k_kb0 = (uint32_t)((k_m & 1) << 4);

    const float SC2 = 0.18033688011f;   // 0.125 * log2(e)
    const int nch = S / 64;

    for (int c = 0; c < nch; c++) {
        if (c + 1 < nch) cp_wait<1>(); else cp_wait<0>();
        __syncthreads();
        const uint32_t stK = sb + (c % 3) * ATT_STG;
        const uint32_t stV = sb + (c > 0 ? (c - 1) % 3 : 0) * ATT_STG;

        // ---- QK^T (3-term split) -> s ----
        float s[8][4];
#pragma unroll
        for (int nt = 0; nt < 8; nt++)
#pragma unroll
            for (int e = 0; e < 4; e++) s[nt][e] = 0.0f;

#pragma unroll
        for (int j = 0; j < 4; j++) {
#pragma unroll
            for (int p = 0; p < 4; p++) {
                uint32_t off = swz((uint32_t)((p * 16 + k_row0) * 128 + j * 32 + k_kb0));
                uint32_t kb[4], kbl[4];
                ldsm4(kb, stK + off);
                ldsm4(kbl, stK + 8192 + off);
                mma16816(s[2 * p], qfh[j], kb);
                mma16816(s[2 * p], qfl[j], kb);
                mma16816(s[2 * p], qfh[j], kbl);
                mma16816(s[2 * p + 1], qfh[j], kb + 2);
                mma16816(s[2 * p + 1], qfl[j], kb + 2);
                mma16816(s[2 * p + 1], qfh[j], kbl + 2);
            }
        }

        auto pv_block = [&](int j) {
#pragma unroll
            for (int db = 0; db < 4; db++) {
                uint32_t off = swz((uint32_t)((j * 16 + (lane & 15)) * 128
                                              + (db * 2 + (lane >> 4)) * 16));
                uint32_t vfh[4], vfl[4];
                ldsm4t(vfh, stV + 16384 + off);
                ldsm4t(vfl, stV + 24576 + off);
                mma16816(o[db * 2], pah_s[j], vfh);
                mma16816(o[db * 2], pal_s[j], vfh);
                mma16816(o[db * 2], pah_s[j], vfl);
                mma16816(o[db * 2 + 1], pah_s[j], vfh + 2);
                mma16816(o[db * 2 + 1], pal_s[j], vfh + 2);
                mma16816(o[db * 2 + 1], pah_s[j], vfl + 2);
            }
        };

        // ---- phase 1: mask + scale into log2 domain ----
        const int* mr = mbase + c * 64;
#pragma unroll
        for (int nt = 0; nt < 8; nt++) {
            int2 ma = *(const int2*)(mr + nt * 8);
            int2 mb2 = *(const int2*)(mr + 8 * S + nt * 8);
            s[nt][0] = (ma.x == 0) ? -14427.0f : s[nt][0] * SC2;
            s[nt][1] = (ma.y == 0) ? -14427.0f : s[nt][1] * SC2;
            s[nt][2] = (mb2.x == 0) ? -14427.0f : s[nt][2] * SC2;
            s[nt][3] = (mb2.y == 0) ? -14427.0f : s[nt][3] * SC2;
        }

        pv_block(0);

        // ---- phase 2: local max reduce ----
        float mx0 = -1e30f, mx1 = -1e30f;
#pragma unroll
        for (int nt = 0; nt < 8; nt++) {
            mx0 = fmaxf(mx0, fmaxf(s[nt][0], s[nt][1]));
            mx1 = fmaxf(mx1, fmaxf(s[nt][2], s[nt][3]));
        }

        pv_block(1);

        // ---- phase 3: max shuffles + new maxima ----
        mx0 = fmaxf(mx0, __shfl_xor_sync(0xffffffffu, mx0, 1));
        mx0 = fmaxf(mx0, __shfl_xor_sync(0xffffffffu, mx0, 2));
        mx1 = fmaxf(mx1, __shfl_xor_sync(0xffffffffu, mx1, 1));
        mx1 = fmaxf(mx1, __shfl_xor_sync(0xffffffffu, mx1, 2));
        float mn0 = fmaxf(m0, mx0), mn1 = fmaxf(m1, mx1);
        float d0 = m0 - mn0, d1 = m1 - mn1;
        bool unchanged = (d0 == 0.0f) && (d1 == 0.0f);
        m0 = mn0;
        m1 = mn1;

        pv_block(2);

        // ---- phase 4: exponentials (first half) ----
        float rs0 = 0.0f, rs1 = 0.0f;
#pragma unroll
        for (int nt = 0; nt < 4; nt++) {
            s[nt][0] = ex2(s[nt][0] - mn0);
            s[nt][1] = ex2(s[nt][1] - mn0);
            s[nt][2] = ex2(s[nt][2] - mn1);
            s[nt][3] = ex2(s[nt][3] - mn1);
            rs0 += s[nt][0] + s[nt][1];
            rs1 += s[nt][2] + s[nt][3];
        }

        pv_block(3);

        // ---- phase 5: exponentials (second half) + sums ----
#pragma unroll
        for (int nt = 4; nt < 8; nt++) {
            s[nt][0] = ex2(s[nt][0] - mn0);
            s[nt][1] = ex2(s[nt][1] - mn0);
            s[nt][2] = ex2(s[nt][2] - mn1);
            s[nt][3] = ex2(s[nt][3] - mn1);
            rs0 += s[nt][0] + s[nt][1];
            rs1 += s[nt][2] + s[nt][3];
        }
        rs0 += __shfl_xor_sync(0xffffffffu, rs0, 1);
        rs0 += __shfl_xor_sync(0xffffffffu, rs0, 2);
        rs1 += __shfl_xor_sync(0xffffffffu, rs1, 1);
        rs1 += __shfl_xor_sync(0xffffffffu, rs1, 2);

        // ---- join: l update + o-rescale, skipped warp-uniformly when m
        //      unchanged (cr == 1 exactly; multiply elided, bit-identical) ----
        if (__all_sync(0xffffffffu, unchanged)) {
            l0 += rs0;
            l1 += rs1;
        } else {
            float cr0 = ex2(d0), cr1 = ex2(d1);
            l0 = l0 * cr0 + rs0;
            l1 = l1 * cr1 + rs1;
#pragma unroll
            for (int nt = 0; nt < 8; nt++) {
                o[nt][0] *= cr0;
                o[nt][1] *= cr0;
                o[nt][2] *= cr1;
                o[nt][3] *= cr1;
            }
        }

        // ---- split P -> persistent fragments (after last pah_s read) ----
#pragma unroll
        for (int j = 0; j < 4; j++) {
            splitpack(s[2 * j][0], s[2 * j][1], pah_s[j][0], pal_s[j][0]);
            splitpack(s[2 * j][2], s[2 * j][3], pah_s[j][1], pal_s[j][1]);
            splitpack(s[2 * j + 1][0], s[2 * j + 1][1], pah_s[j][2], pal_s[j][2]);
            splitpack(s[2 * j + 1][2], s[2 * j + 1][3], pah_s[j][3], pal_s[j][3]);
        }

        __syncthreads();
        if (c + 2 < nch) fillkv((c + 2) % 3, c + 2);
    }

    // ---- final pending PV(nch-1) ----
    {
        const uint32_t stV = sb + ((nch - 1) % 3) * ATT_STG;
#pragma unroll
        for (int j = 0; j < 4; j++) {
#pragma unroll
            for (int db = 0; db < 4; db++) {
                uint32_t off = swz((uint32_t)((j * 16 + (lane & 15)) * 128
                                              + (db * 2 + (lane >> 4)) * 16));
                uint32_t vfh[4], vfl[4];
                ldsm4t(vfh, stV + 16384 + off);
                ldsm4t(vfl, stV + 24576 + off);
                mma16816(o[db * 2], pah_s[j], vfh);
                mma16816(o[db * 2], pal_s[j], vfh);
                mma16816(o[db * 2], pah_s[j], vfl);
                mma16816(o[db * 2 + 1], pah_s[j], vfh + 2);
                mma16816(o[db * 2 + 1], pal_s[j], vfh + 2);
                mma16816(o[db * 2 + 1], pah_s[j], vfl + 2);
            }
        }
    }

    const float i0 = 1.0f / l0, i1 = 1.0f / l1;
    const size_t ob = (size_t)(b * S + grow) * H_DIM + h * DHEAD + 2 * (lane & 3);
#pragma unroll
    for (int nt = 0; nt < 8; nt++) {
        uint32_t h0, lo0, h1, lo1;
        splitpack(o[nt][0] * i0, o[nt][1] * i0, h0, lo0);
        splitpack(o[nt][2] * i1, o[nt][3] * i1, h1, lo1);
        *(uint32_t*)(Oh + ob + nt * 8) = h0;
        *(uint32_t*)(Ol + ob + nt * 8) = lo0;
        *(uint32_t*)(Oh + ob + 8 * H_DIM + nt * 8) = h1;
        *(uint32_t*)(Ol + ob + 8 * H_DIM + nt * 8) = lo1;
    }
}

// ---------------- launch ---------------------------------------------------
extern "C" void kernel_launch(void* const* d_in, const int* in_sizes, int n_in,
                              void* d_out, int out_size)
{
    const float* q   = (const float*)d_in[0];
    const float* k   = (const float*)d_in[1];
    const float* v   = (const float*)d_in[2];
    const int*   msk = (const int*)d_in[3];
    const float* w_q = (const float*)d_in[4];
    const float* b_q = (const float*)d_in[5];
    const float* w_k = (const float*)d_in[6];
    const float* b_k = (const float*)d_in[7];
    const float* w_v = (const float*)d_in[8];
    const float* b_v = (const float*)d_in[9];
    const float* w_o = (const float*)d_in[10];
    const float* b_o = (const float*)d_in[11];
    float* out = (float*)d_out;

    const int BS = in_sizes[0] / H_DIM;
    const int S  = in_sizes[3] / BS;
    const int B  = BS / S;
    const int M  = BS;
    const int n_elem = M * H_DIM;

    __nv_bfloat16 *xh, *xl, *qh, *ql, *kh, *kl, *vh, *vl, *oh, *ol, *wh, *wl;
    cudaGetSymbolAddress((void**)&xh, g_xh);
    cudaGetSymbolAddress((void**)&xl, g_xl);
    cudaGetSymbolAddress((void**)&qh, g_qh);
    cudaGetSymbolAddress((void**)&ql, g_ql);
    cudaGetSymbolAddress((void**)&kh, g_kh);
    cudaGetSymbolAddress((void**)&kl, g_kl);
    cudaGetSymbolAddress((void**)&vh, g_vh);
    cudaGetSymbolAddress((void**)&vl, g_vl);
    cudaGetSymbolAddress((void**)&oh, g_oh);
    cudaGetSymbolAddress((void**)&ol, g_ol);
    cudaGetSymbolAddress((void**)&wh, g_wh);
    cudaGetSymbolAddress((void**)&wl, g_wl);

    cudaFuncSetAttribute(hmma_gemm_kernel,
                         cudaFuncAttributeMaxDynamicSharedMemorySize, GEMM_SMEM);
    cudaFuncSetAttribute(hmma_attn_kernel,
                         cudaFuncAttributeMaxDynamicSharedMemorySize, ATT_SMEM);

    const size_t WSZ = 1024 * 1024;

    // all conversions in ONE launch (weights z=0..3, activations z=4..15)
    conv_all_kernel<<<dim3(32, 32, 16), 256>>>(
        w_q, w_k, w_v, w_o, q, k, v, wh, wl, xh, xl, n_elem);

    // QKV projections in ONE launch (z = 0,1,2)
    {
        GemmArgs ga;
        for (int z = 0; z < 3; z++) {
            ga.Ah[z] = xh + (size_t)z * n_elem;
            ga.Al[z] = xl + (size_t)z * n_elem;
            ga.Bh[z] = wh + (size_t)z * WSZ;
            ga.Bl[z] = wl + (size_t)z * WSZ;
            ga.Cf[z] = nullptr;
        }
        ga.bias[0] = b_q; ga.bias[1] = b_k; ga.bias[2] = b_v;
        ga.Ch[0] = qh; ga.Cl[0] = ql;
        ga.Ch[1] = kh; ga.Cl[1] = kl;
        ga.Ch[2] = vh; ga.Cl[2] = vl;
        hmma_gemm_kernel<<<dim3(H_DIM / 128, M / 128, 3), 256, GEMM_SMEM>>>(ga);
    }

    // attention: interleaved deferred-PV pipeline, 2 CTAs/SM
    hmma_attn_kernel<<<dim3(S / 64, NHEAD, B), 128, ATT_SMEM>>>(
        qh, ql, kh, kl, vh, vl, msk, oh, ol, S);

    // O projection -> fp32 out
    {
        GemmArgs ga;
        ga.Ah[0] = oh; ga.Al[0] = ol;
        ga.Bh[0] = wh + 3 * WSZ; ga.Bl[0] = wl + 3 * WSZ;
        ga.bias[0] = b_o;
        ga.Cf[0] = out; ga.Ch[0] = nullptr; ga.Cl[0] = nullptr;
        ga.Ah[1] = ga.Ah[2] = oh; ga.Al[1] = ga.Al[2] = ol;
        ga.Bh[1] = ga.Bh[2] = wh; ga.Bl[1] = ga.Bl[2] = wl;
        ga.bias[1] = ga.bias[2] = b_o;
        ga.Cf[1] = ga.Cf[2] = nullptr;
        ga.Ch[1] = ga.Ch[2] = nullptr; ga.Cl[1] = ga.Cl[2] = nullptr;
        hmma_gemm_kernel<<<dim3(H_DIM / 128, M / 128, 1), 256, GEMM_SMEM>>>(ga);
    }
}